// round 1
// baseline (speedup 1.0000x reference)
#include <cuda_runtime.h>
#include <math.h>

// Problem constants
#define NIMG   4
#define HW     48
#define CH     3
#define NPIX   (HW*HW*CH)        // 6912 per image
#define NTOT   (NIMG*NPIX)       // 27648
#define KS     21
#define KR     10
#define KTAPS  (KS*KS)           // 441

// Table config
#define TPTS   513               // x grid: t/512, t=0..512
#define NBC    32                // b-chunks
#define BLEN   (NPIX/NBC)        // 216

// Scratch (device globals; no allocation)
__device__ float d_kern[3][CH][KTAPS];     // [m,w,g][channel][tap]
__device__ float d_first[NTOT];            // conv(inputs, Km), NHWC
__device__ float d_F[NTOT];                // exp(-2*conv(inputs, Kg)), NHWC
__device__ float d_partial[NIMG*TPTS*NBC];
__device__ float d_table[NIMG*TPTS];
__device__ float d_diff[NTOT];             // interpolated difference field, NHWC

__device__ __forceinline__ float frcp(float x) {
    float r;
    asm("rcp.approx.f32 %0, %1;" : "=f"(r) : "f"(x));
    return r;
}

// ---------------------------------------------------------------------------
// A: build the 9 normalized Gaussian kernels. 9 warps, one per (type, channel).
// ---------------------------------------------------------------------------
__global__ void k_kernels(const float* __restrict__ gm,
                          const float* __restrict__ gw,
                          const float* __restrict__ gg) {
    int warp = threadIdx.x >> 5;
    int lane = threadIdx.x & 31;
    if (warp >= 9) return;
    int type = warp / 3, f = warp % 3;
    float gamma = (type == 0 ? gm : (type == 1 ? gw : gg))[f];
    float sigma = 1.0f / gamma;
    float inv2s2 = 1.0f / (2.0f * sigma * sigma);
    // linspace(0, 21/32, 21): step = (21/32)/20, mean = 21/64
    const float step = (21.0f / 32.0f) / 20.0f;
    const float mean = 21.0f / 64.0f;

    float vals[14];
    float ss = 0.0f;
    int j = 0;
    for (int i = lane; i < KTAPS; i += 32, j++) {
        int iy = i / KS, ix = i % KS;
        float dx = (float)ix * step - mean;
        float dy = (float)iy * step - mean;
        float v = expf(-(dx * dx + dy * dy) * inv2s2);  // amp cancels in L2 norm
        vals[j] = v;
        ss += v * v;
    }
    #pragma unroll
    for (int o = 16; o > 0; o >>= 1)
        ss += __shfl_xor_sync(0xffffffffu, ss, o);
    float s = 1.0f / sqrtf(ss);
    j = 0;
    for (int i = lane; i < KTAPS; i += 32, j++)
        d_kern[type][f][i] = vals[j] * s;
}

// ---------------------------------------------------------------------------
// B: fused depthwise convs with Km and Kg; store first_term and F=exp(-2*blur).
// Thread mapping planar: idx = ((n*3+c)*48+y)*48+x  (uniform kernel per warp)
// ---------------------------------------------------------------------------
__global__ void k_conv_mg(const float* __restrict__ in) {
    int idx = blockIdx.x * blockDim.x + threadIdx.x;
    if (idx >= NTOT) return;
    int x = idx % HW;
    int y = (idx / HW) % HW;
    int c = (idx / (HW * HW)) % CH;
    int n = idx / NPIX;

    const float* km = d_kern[0][c];
    const float* kg = d_kern[2][c];
    const float* img = in + n * NPIX;

    float sm = 0.0f, sg = 0.0f;
    for (int ky = 0; ky < KS; ky++) {
        int iy = y + ky - KR;
        if ((unsigned)iy >= (unsigned)HW) continue;
        const float* row = img + iy * (HW * CH);
        const float* kmr = km + ky * KS;
        const float* kgr = kg + ky * KS;
        #pragma unroll
        for (int kx = 0; kx < KS; kx++) {
            int ix = x + kx - KR;
            if ((unsigned)ix < (unsigned)HW) {
                float v = row[ix * CH + c];
                sm = fmaf(v, kmr[kx], sm);
                sg = fmaf(v, kgr[kx], sg);
            }
        }
    }
    int oidx = ((n * HW + y) * HW + x) * CH + c;   // NHWC
    d_first[oidx] = sm;
    d_F[oidx] = __expf(-2.0f * sg);
}

// ---------------------------------------------------------------------------
// C: table partial sums. grid = (xgroups=5, bchunks=32, images=4), block=128.
// partial[n][t][bc] = sum over chunk of 1/(1 + e^{2x_t} * e^{-2b})
// ---------------------------------------------------------------------------
__global__ void k_table_partial() {
    __shared__ float sF[BLEN];
    int n  = blockIdx.z;
    int bc = blockIdx.y;
    int xg = blockIdx.x;

    const float* Fb = d_F + n * NPIX + bc * BLEN;
    for (int i = threadIdx.x; i < BLEN; i += blockDim.x)
        sF[i] = Fb[i];
    __syncthreads();

    int t = xg * 128 + threadIdx.x;
    if (t >= TPTS) return;
    float E = __expf(2.0f * (float)t * (1.0f / 512.0f));

    float a0 = 0.f, a1 = 0.f, a2 = 0.f, a3 = 0.f;
    #pragma unroll 4
    for (int i = 0; i < BLEN; i += 4) {
        a0 += frcp(fmaf(E, sF[i + 0], 1.0f));
        a1 += frcp(fmaf(E, sF[i + 1], 1.0f));
        a2 += frcp(fmaf(E, sF[i + 2], 1.0f));
        a3 += frcp(fmaf(E, sF[i + 3], 1.0f));
    }
    d_partial[(n * TPTS + t) * NBC + bc] = (a0 + a1) + (a2 + a3);
}

// ---------------------------------------------------------------------------
// D: reduce partials -> table[n][t] = 1 - (2/NPIX) * sum_b rcp
// ---------------------------------------------------------------------------
__global__ void k_table_reduce() {
    int i = blockIdx.x * blockDim.x + threadIdx.x;
    if (i >= NIMG * TPTS) return;
    const float* p = d_partial + i * NBC;
    float s = 0.0f;
    #pragma unroll
    for (int j = 0; j < NBC; j++) s += p[j];
    d_table[i] = 1.0f - s * (2.0f / (float)NPIX);
}

// ---------------------------------------------------------------------------
// E: difference field via linear interpolation of per-image table
// ---------------------------------------------------------------------------
__global__ void k_diff(const float* __restrict__ in) {
    int idx = blockIdx.x * blockDim.x + threadIdx.x;
    if (idx >= NTOT) return;
    int n = idx / NPIX;
    float x = in[idx];
    float u = x * 512.0f;
    u = fminf(fmaxf(u, 0.0f), 511.9999f);
    int i0 = (int)u;
    float fr = u - (float)i0;
    const float* T = d_table + n * TPTS;
    float t0 = T[i0], t1 = T[i0 + 1];
    d_diff[idx] = fmaf(t1 - t0, fr, t0);
}

// ---------------------------------------------------------------------------
// F: conv(diff, Kw) and final output = first_term - second_term
// ---------------------------------------------------------------------------
__global__ void k_conv_w(float* __restrict__ out) {
    int idx = blockIdx.x * blockDim.x + threadIdx.x;
    if (idx >= NTOT) return;
    int x = idx % HW;
    int y = (idx / HW) % HW;
    int c = (idx / (HW * HW)) % CH;
    int n = idx / NPIX;

    const float* kw = d_kern[1][c];
    const float* img = d_diff + n * NPIX;   // NHWC

    float sw = 0.0f;
    for (int ky = 0; ky < KS; ky++) {
        int iy = y + ky - KR;
        if ((unsigned)iy >= (unsigned)HW) continue;
        const float* row = img + iy * (HW * CH);
        const float* kwr = kw + ky * KS;
        #pragma unroll
        for (int kx = 0; kx < KS; kx++) {
            int ix = x + kx - KR;
            if ((unsigned)ix < (unsigned)HW) {
                sw = fmaf(row[ix * CH + c], kwr[kx], sw);
            }
        }
    }
    int oidx = ((n * HW + y) * HW + x) * CH + c;
    out[oidx] = d_first[oidx] - sw;
}

// ---------------------------------------------------------------------------
extern "C" void kernel_launch(void* const* d_in, const int* in_sizes, int n_in,
                              void* d_out, int out_size) {
    const float* in = (const float*)d_in[0];
    const float* gm = (const float*)d_in[1];
    const float* gw = (const float*)d_in[2];
    const float* gg = (const float*)d_in[3];
    float* out = (float*)d_out;

    k_kernels<<<1, 288>>>(gm, gw, gg);

    int nb = (NTOT + 255) / 256;
    k_conv_mg<<<nb, 256>>>(in);

    dim3 gC((TPTS + 127) / 128, NBC, NIMG);   // (5, 32, 4)
    k_table_partial<<<gC, 128>>>();

    k_table_reduce<<<(NIMG * TPTS + 127) / 128, 128>>>();

    k_diff<<<nb, 256>>>(in);

    k_conv_w<<<nb, 256>>>(out);
}

// round 2
// speedup vs baseline: 3.5366x; 3.5366x over previous
#include <cuda_runtime.h>
#include <math.h>

// Problem constants
#define NIMG   4
#define HW     48
#define CH     3
#define PLANE  (HW*HW)            // 2304
#define NPIX   (PLANE*CH)         // 6912 per image
#define KS     21
#define KR     10

// Config
#define TPTS   257                // tanh-mean table points on [0,1]
#define GRID   144                // 1 block/SM guaranteed (<=148) -> safe spin barrier
#define TB     256
#define YT     4                  // output rows per conv tile (144 = 4n*3c*12 ytiles)
#define TROWS  (YT + KS - 1)      // 24
#define TCOLS  (HW + KS - 1)      // 68

// Scratch (device globals; no allocation)
__device__ float d_F[NIMG * NPIX];        // exp(-2*G(inputs)), planar [n][c][y][x]
__device__ float d_table[NIMG * TPTS];
__device__ unsigned g_cnt = 0;
__device__ volatile unsigned g_gen = 0;

// Shared pool layout (floats):
//  P1:  IN @0 (1632), H @1700 (1152), KG @2900 (21)
//  P2:  F image @0 (6912)
//  P3:  IN @0 (1632), DF @1632 (1632), HM @3264 (1152), HW @4416 (1152),
//       KM @5568 (21), KW @5600 (21), TBL @5632 (257)
#define SP_IN   0
#define SP_H    1700
#define SP_KG   2900
#define SP_DF   1632
#define SP_HM   3264
#define SP_HW   4416
#define SP_KM   5568
#define SP_KW   5600
#define SP_TBL  5632

__device__ __forceinline__ float frcp(float x) {
    float r;
    asm("rcp.approx.f32 %0, %1;" : "=f"(r) : "f"(x));
    return r;
}

// Grid-wide barrier (sense via monotonically increasing generation; safe
// across graph replays, all GRID blocks co-resident by construction).
__device__ __forceinline__ void gridbar() {
    __syncthreads();
    __threadfence();
    if (threadIdx.x == 0) {
        unsigned gen = g_gen;
        if (atomicAdd(&g_cnt, 1u) == GRID - 1) {
            g_cnt = 0;
            __threadfence();
            g_gen = gen + 1;
        } else {
            while (g_gen == gen) {}
        }
    }
    __syncthreads();
    __threadfence();
}

// One warp builds a unit-L2 1D Gaussian (the 2D kernel is exactly the outer
// product of this with itself: k2d/||k2d||_2 = g1 (x) g1).
__device__ __forceinline__ void make_k1d(float gamma, float* out) {
    int lane = threadIdx.x & 31;
    float inv2s2 = 0.5f * gamma * gamma;          // 1/(2 sigma^2), sigma=1/gamma
    const float step = (21.0f / 32.0f) / 20.0f;   // linspace(0, KS/FS, KS) step
    const float mean = 21.0f / 64.0f;             // KS/(2*FS)
    float v = 0.0f;
    if (lane < KS) {
        float d = (float)lane * step - mean;
        v = expf(-d * d * inv2s2);                // amp cancels in L2 norm
    }
    float ss = v * v;
    #pragma unroll
    for (int o = 16; o > 0; o >>= 1) ss += __shfl_xor_sync(0xffffffffu, ss, o);
    if (lane < KS) out[lane] = v * rsqrtf(ss);
}

__global__ __launch_bounds__(TB, 1)
void inrf_fused(const float* __restrict__ in,
                const float* __restrict__ gm,
                const float* __restrict__ gw,
                const float* __restrict__ gg,
                float* __restrict__ out) {
    __shared__ float sp[NPIX];   // 27648 B

    const int tid  = threadIdx.x;
    const int warp = tid >> 5;
    const int lane = tid & 31;

    // Conv-phase block decomposition: 144 = 4n * 3c * 12 ytiles
    const int b   = blockIdx.x;
    const int n   = b / 36;
    const int rem = b % 36;
    const int c   = rem / 12;
    const int y0  = (rem % 12) * YT;

    // ---------------- Phase 1: F = exp(-2 * G(inputs)), separable conv -----
    if (warp == 0) make_k1d(gg[c], sp + SP_KG);

    // zero-padded input tile (rows y0-10..y0+13, cols -10..57), channel c
    for (int i = tid; i < TROWS * TCOLS; i += TB) {
        int r  = i / TCOLS;
        int xc = i % TCOLS - KR;
        int yy = y0 - KR + r;
        float v = 0.0f;
        if ((unsigned)yy < HW && (unsigned)xc < HW)
            v = in[((n * HW + yy) * HW + xc) * CH + c];
        sp[SP_IN + i] = v;
    }
    __syncthreads();

    // horizontal pass
    for (int i = tid; i < TROWS * HW; i += TB) {
        int r = i / HW, x = i % HW;
        const float* row = sp + SP_IN + r * TCOLS + x;
        float s = 0.0f;
        #pragma unroll
        for (int k = 0; k < KS; k++) s = fmaf(row[k], sp[SP_KG + k], s);
        sp[SP_H + i] = s;
    }
    __syncthreads();

    // vertical pass -> F (planar layout for fast phase-2 streaming)
    for (int i = tid; i < YT * HW; i += TB) {
        int yo = i / HW, x = i % HW;
        float s = 0.0f;
        #pragma unroll
        for (int k = 0; k < KS; k++)
            s = fmaf(sp[SP_H + (yo + k) * HW + x], sp[SP_KG + k], s);
        d_F[(n * CH + c) * PLANE + (y0 + yo) * HW + x] = __expf(-2.0f * s);
    }

    gridbar();

    // ---------------- Phase 2: table[n][t] = mean_b tanh(x_t - b) ----------
    // tanh(x-b) = 1 - 2/(1 + e^{2x} e^{-2b});   F = e^{-2b} precomputed.
    {
        const int n2 = blockIdx.x & 3;                 // 36 blocks per image
        const int t  = (blockIdx.x >> 2) * 8 + warp;   // one table point per warp

        const float4* Fv  = (const float4*)(d_F + n2 * NPIX);
        float4*       spv = (float4*)sp;
        for (int i = tid; i < NPIX / 4; i += TB) spv[i] = Fv[i];
        __syncthreads();

        if (t < TPTS) {
            float E = __expf(2.0f * (float)t * (1.0f / (TPTS - 1)));
            float a0 = 0.f, a1 = 0.f, a2 = 0.f, a3 = 0.f;
            #pragma unroll 2
            for (int i = lane; i < NPIX; i += 128) {   // 54 exact iterations
                a0 += frcp(fmaf(E, sp[i],      1.0f));
                a1 += frcp(fmaf(E, sp[i + 32], 1.0f));
                a2 += frcp(fmaf(E, sp[i + 64], 1.0f));
                a3 += frcp(fmaf(E, sp[i + 96], 1.0f));
            }
            float s = (a0 + a1) + (a2 + a3);
            #pragma unroll
            for (int o = 16; o > 0; o >>= 1)
                s += __shfl_xor_sync(0xffffffffu, s, o);
            if (lane == 0)
                d_table[n2 * TPTS + t] = 1.0f - s * (2.0f / (float)NPIX);
        }
    }

    gridbar();

    // ---------------- Phase 3: out = M(inputs) - W(diff) -------------------
    if (warp == 0)      make_k1d(gm[c], sp + SP_KM);
    else if (warp == 1) make_k1d(gw[c], sp + SP_KW);

    for (int i = tid; i < TPTS; i += TB)
        sp[SP_TBL + i] = d_table[n * TPTS + i];
    __syncthreads();   // table visible before diff interp below

    // zero-padded (input, diff) tiles; diff = lerp of per-image table at x
    for (int i = tid; i < TROWS * TCOLS; i += TB) {
        int r  = i / TCOLS;
        int xc = i % TCOLS - KR;
        int yy = y0 - KR + r;
        float v = 0.0f, d = 0.0f;
        if ((unsigned)yy < HW && (unsigned)xc < HW) {
            v = in[((n * HW + yy) * HW + xc) * CH + c];
            float u = v * (float)(TPTS - 1);
            u = fminf(fmaxf(u, 0.0f), (float)(TPTS - 1) - 1e-3f);
            int   i0 = (int)u;
            float fr = u - (float)i0;
            float t0 = sp[SP_TBL + i0], t1 = sp[SP_TBL + i0 + 1];
            d = fmaf(t1 - t0, fr, t0);
        }
        sp[SP_IN + i] = v;
        sp[SP_DF + i] = d;
    }
    __syncthreads();

    // horizontal passes (both convs)
    for (int i = tid; i < TROWS * HW; i += TB) {
        int r = i / HW, x = i % HW;
        const float* rin = sp + SP_IN + r * TCOLS + x;
        const float* rdf = sp + SP_DF + r * TCOLS + x;
        float sm = 0.0f, sw = 0.0f;
        #pragma unroll
        for (int k = 0; k < KS; k++) {
            sm = fmaf(rin[k], sp[SP_KM + k], sm);
            sw = fmaf(rdf[k], sp[SP_KW + k], sw);
        }
        sp[SP_HM + i] = sm;
        sp[SP_HW + i] = sw;
    }
    __syncthreads();

    // vertical passes + final subtraction (L = 1)
    for (int i = tid; i < YT * HW; i += TB) {
        int yo = i / HW, x = i % HW;
        float sm = 0.0f, sw = 0.0f;
        #pragma unroll
        for (int k = 0; k < KS; k++) {
            sm = fmaf(sp[SP_HM + (yo + k) * HW + x], sp[SP_KM + k], sm);
            sw = fmaf(sp[SP_HW + (yo + k) * HW + x], sp[SP_KW + k], sw);
        }
        out[((n * HW + y0 + yo) * HW + x) * CH + c] = sm - sw;
    }
}

extern "C" void kernel_launch(void* const* d_in, const int* in_sizes, int n_in,
                              void* d_out, int out_size) {
    const float* in = (const float*)d_in[0];
    const float* gm = (const float*)d_in[1];
    const float* gw = (const float*)d_in[2];
    const float* gg = (const float*)d_in[3];
    float* out = (float*)d_out;

    inrf_fused<<<GRID, TB>>>(in, gm, gw, gg, out);
}